// round 17
// baseline (speedup 1.0000x reference)
#include <cuda_runtime.h>

// RPE MHA, sm_100a. B=2, N=M=512, C=256, H=8, D=32.
// scores_p = embed . wq with wq = Wp-projected q (avoids projecting embed).
// R16 = R14 fused (best known) + 512-thread side GEMMs (16 warps/CTA to
// hide LDS/barrier latency; side kernels were occ-starved at 8 warps).

#define SCALE_Q 0.17677669529663687f  // 32^-0.5, folded into q projection

__device__ float g_q[1024 * 256];
__device__ float g_k[1024 * 256];
__device__ float g_v[1024 * 256];
__device__ float g_wq[8 * 1024 * 256];     // [h][bn][c]
__device__ float g_se[16 * 512 * 512];     // [b*8+h][n][m]
__device__ float g_hid[1024 * 256];        // [bn][c]

// fused kernel dynamic smem: ES ring 16384 floats + S 8*520 floats
#define FK_SMEM_BYTES ((16384 + 8 * 520) * 4)

// ---------------------------------------------------------------------------
// packed f32x2 helpers (Blackwell dual-FMA)
// ---------------------------------------------------------------------------
#define FMA2(d, a, b, c) \
    asm("fma.rn.f32x2 %0, %1, %2, %3;" : "=l"(d) : "l"(a), "l"(b), "l"(c))
#define MUL2(d, a, b) \
    asm("mul.rn.f32x2 %0, %1, %2;" : "=l"(d) : "l"(a), "l"(b))
#define UNPACK2(lo, hi, v) \
    asm("mov.b64 {%0, %1}, %2;" : "=f"(lo), "=f"(hi) : "l"(v))
#define PACK2(d, lo, hi) \
    asm("mov.b64 %0, {%1, %2};" : "=l"(d) : "f"(lo), "f"(hi))

// ---------------------------------------------------------------------------
// cp.async helpers
// ---------------------------------------------------------------------------
__device__ __forceinline__ void cp16(float* dst_smem, const float* src)
{
    unsigned d = (unsigned)__cvta_generic_to_shared(dst_smem);
    asm volatile("cp.async.cg.shared.global [%0], [%1], 16;" :: "r"(d), "l"(src));
}
__device__ __forceinline__ void cp_commit()
{
    asm volatile("cp.async.commit_group;");
}
__device__ __forceinline__ void cp_wait3()
{
    asm volatile("cp.async.wait_group 3;");
}

// ---------------------------------------------------------------------------
// 32x64 tiled fp32 GEMM, 512 threads (16 warps), K-tile 32, register
// double-buffered. Thread -> 1 row x 4 cols (single float4 epilogue store).
// BT=false: C = A[m][k] @ B[k][n].  BT=true: C = A[m][k] @ B[n][k].
// M multiple of 32, N multiple of 64, K multiple of 32.
// ---------------------------------------------------------------------------
template <bool BT>
__device__ __forceinline__ void gemm_body(
    const float* __restrict__ A, int lda,
    const float* __restrict__ B, int ldb,
    float* __restrict__ C, int ldc,
    int K, float scale, const float* __restrict__ bias)
{
    __shared__ float As[32][36];
    __shared__ float Bs[32][68];

    const int tid = threadIdx.x;
    const int m0 = blockIdx.x * 32;
    const int n0 = blockIdx.y * 64;

    const int ar  = tid >> 4;           // 0..31  A row
    const int ac  = (tid & 15) << 1;    // 0..30  A k-col (float2)
    const int bkr = tid >> 4;           // 0..31  B k-row (NN)
    const int bnc = (tid & 15) << 2;    // 0..60  B n-col (NN)
    const int nr  = tid >> 3;           // 0..63  B n-row (NT)
    const int nc  = (tid & 7) << 2;     // 0..28  B k-col (NT)
    const int ty  = tid >> 4;           // row
    const int tx  = tid & 15;           // col group (4 cols)

    float acc[4] = {0.f, 0.f, 0.f, 0.f};

    // prime first K-tile
    float2 a2 = *(const float2*)(A + (long)(m0 + ar) * lda + ac);
    float4 b4;
    if (BT)
        b4 = *(const float4*)(B + (long)(n0 + nr) * ldb + nc);
    else
        b4 = *(const float4*)(B + (long)bkr * ldb + n0 + bnc);

    for (int k0 = 0; k0 < K; k0 += 32) {
        *(float2*)&As[ar][ac] = a2;
        if (BT) {
            Bs[nc + 0][nr] = b4.x;
            Bs[nc + 1][nr] = b4.y;
            Bs[nc + 2][nr] = b4.z;
            Bs[nc + 3][nr] = b4.w;
        } else {
            *(float4*)&Bs[bkr][bnc] = b4;
        }
        __syncthreads();

        if (k0 + 32 < K) {
            a2 = *(const float2*)(A + (long)(m0 + ar) * lda + k0 + 32 + ac);
            if (BT)
                b4 = *(const float4*)(B + (long)(n0 + nr) * ldb + k0 + 32 + nc);
            else
                b4 = *(const float4*)(B + (long)(k0 + 32 + bkr) * ldb + n0 + bnc);
        }

#pragma unroll
        for (int kk = 0; kk < 32; kk++) {
            float a = As[ty][kk];
            float4 bb = *(const float4*)&Bs[kk][tx * 4];
            acc[0] += a * bb.x;
            acc[1] += a * bb.y;
            acc[2] += a * bb.z;
            acc[3] += a * bb.w;
        }
        __syncthreads();
    }

    float4 o;
    o.x = acc[0] * scale;
    o.y = acc[1] * scale;
    o.z = acc[2] * scale;
    o.w = acc[3] * scale;
    if (bias) {
        const float* bp = bias + n0 + tx * 4;
        o.x += bp[0]; o.y += bp[1]; o.z += bp[2]; o.w += bp[3];
    }
    *(float4*)(C + (long)(m0 + ty) * ldc + n0 + tx * 4) = o;
}

// q/k/v projections batched over grid.z
__global__ void __launch_bounds__(512) k_gemm_qkv(
    const float* Aq, const float* Ak, const float* Av,
    const float* Bq, const float* Bk, const float* Bv,
    float* Cq, float* Ck, float* Cv)
{
    int z = blockIdx.z;
    const float* A = (z == 0) ? Aq : (z == 1) ? Ak : Av;
    const float* B = (z == 0) ? Bq : (z == 1) ? Bk : Bv;
    float*       C = (z == 0) ? Cq : (z == 1) ? Ck : Cv;
    gemm_body<false>(A, 256, B, 256, C, 256, 256,
                     (z == 0) ? SCALE_Q : 1.0f, nullptr);
}

// Combined wq + scores_e (K=32 -> single K-tile). grid (32, 8, 24).
//   z in [0,8):  wq[h] = Q_h @ Wp_h^T     (M=1024, N=256)  [by < 4]
//   z in [8,24): se[b*8+h] = Q_h @ K_h^T  (M=512,  N=512)  [bx < 16]
__global__ void __launch_bounds__(512) k_wq_se(
    const float* __restrict__ q, const float* __restrict__ kmat,
    const float* __restrict__ Wp,
    float* __restrict__ wqo, float* __restrict__ seo)
{
    int z = blockIdx.z;
    if (z < 8) {
        if (blockIdx.y >= 4) return;
        gemm_body<true>(q + z * 32, 256,
                        Wp + z * 32, 256,
                        wqo + (long)z * 262144, 256,
                        32, 1.0f, nullptr);
    } else {
        if (blockIdx.x >= 16) return;
        int zz = z - 8, bb = zz >> 3, hh = zz & 7;
        gemm_body<true>(q + (long)bb * 131072 + hh * 32, 256,
                        kmat + (long)bb * 131072 + hh * 32, 256,
                        seo + (long)zz * 262144, 512,
                        32, 1.0f, nullptr);
    }
}

// out = hidden @ Wout + bout
__global__ void __launch_bounds__(512) k_gemm_out(
    const float* A, const float* B, float* C, const float* bias)
{
    gemm_body<false>(A, 256, B, 256, C, 256, 256, 1.0f, bias);
}

// ---------------------------------------------------------------------------
// Fused scores_p + scores_e(add) + softmax + attn@V -> hidden (R14 version).
// CTA per (b,n), 256 threads. Warp w owns rows m in [64w, 64w+64) for the
// score phase, head w for softmax + PV. cp.async 4-stage x 2-row smem ring.
// Score math in packed f32x2 (dual-FMA).
// ---------------------------------------------------------------------------
__device__ __forceinline__ float reduce8(const float* a, int l)
{
    float r[4];
#pragma unroll
    for (int j = 0; j < 4; j++) {
        float send = (l & 1) ? a[j] : a[j + 4];
        float keep = (l & 1) ? a[j + 4] : a[j];
        r[j] = keep + __shfl_xor_sync(0xFFFFFFFFu, send, 1);
    }
    float r2[2];
#pragma unroll
    for (int j = 0; j < 2; j++) {
        float send = (l & 2) ? r[j] : r[j + 2];
        float keep = (l & 2) ? r[j + 2] : r[j];
        r2[j] = keep + __shfl_xor_sync(0xFFFFFFFFu, send, 2);
    }
    float send = (l & 4) ? r2[0] : r2[1];
    float keep = (l & 4) ? r2[1] : r2[0];
    float s = keep + __shfl_xor_sync(0xFFFFFFFFu, send, 4);
    s += __shfl_xor_sync(0xFFFFFFFFu, s, 8);
    s += __shfl_xor_sync(0xFFFFFFFFu, s, 16);
    return s;
}

// scores for 2 rows; all operands packed f32x2 (ulonglong2 = 2 channel-pairs)
__device__ __forceinline__ void score2(
    ulonglong2 X0, ulonglong2 X1, ulonglong2 Y0, ulonglong2 Y1,
    const ulonglong2* w0, const ulonglong2* w1,
    float* S, int mbase, int hlane, int l)
{
    float a[8], c[8];
#pragma unroll
    for (int h = 0; h < 8; h++) {
        unsigned long long ta, tc;
        MUL2(ta, X0.x, w0[h].x);
        FMA2(ta, X0.y, w0[h].y, ta);
        FMA2(ta, X1.x, w1[h].x, ta);
        FMA2(ta, X1.y, w1[h].y, ta);
        float lo, hi;
        UNPACK2(lo, hi, ta);
        a[h] = lo + hi;
        MUL2(tc, Y0.x, w0[h].x);
        FMA2(tc, Y0.y, w0[h].y, tc);
        FMA2(tc, Y1.x, w1[h].x, tc);
        FMA2(tc, Y1.y, w1[h].y, tc);
        UNPACK2(lo, hi, tc);
        c[h] = lo + hi;
    }
    float sA = reduce8(a, l);
    float sB = reduce8(c, l);
    if (l < 8) {
        S[hlane * 520 + mbase]     = sA;
        S[hlane * 520 + mbase + 1] = sB;
    }
}

__global__ void __launch_bounds__(256, 2) k_fused(
    const float* __restrict__ embed,  // [b][n][m][c]
    const float* __restrict__ wq,     // [h][bn][c]
    const float* __restrict__ se,     // [b*8+h][n][m]
    const float* __restrict__ vmat,   // [b*512+m][c]
    float* __restrict__ hid)          // [bn][c]
{
    extern __shared__ float sm[];
    // ES ring: [8 warps][4 stages][2 rows][256 floats] = 16384 floats (64KB)
    float* S = sm + 16384;

    const int n = blockIdx.x;
    const int b = blockIdx.y;
    const int t = threadIdx.x;
    const int w = t >> 5, l = t & 31;
    const long bn = (long)b * 512 + n;

    // per-lane wq slice, loaded directly as packed pairs
    ulonglong2 w0p[8], w1p[8];
#pragma unroll
    for (int h = 0; h < 8; h++) {
        const float* wp = wq + ((long)h * 1024 + bn) * 256;
        w0p[h] = *(const ulonglong2*)(wp + 4 * l);
        w1p[h] = *(const ulonglong2*)(wp + 128 + 4 * l);
    }
    const int hlane = ((l & 1) << 2) | (l & 2) | ((l & 4) >> 2);

    // warp's 64 embed rows; lane offset folded in
    const float* Eg = embed + bn * 131072L + (long)(w << 6) * 256 + l * 4;
    float* ESw = sm + (w << 11) + l * 4;    // warp ring base + lane offset

    // prime 4 stages (stage s = rows 2s, 2s+1 = 512 floats)
#pragma unroll
    for (int s = 0; s < 4; s++) {
        const float* src = Eg + s * 512;
        float* d = ESw + s * 512;
        cp16(d,       src);
        cp16(d + 128, src + 128);
        cp16(d + 256, src + 256);
        cp16(d + 384, src + 384);
        cp_commit();
    }

#pragma unroll 4
    for (int i = 0; i < 32; i++) {
        const int slot = i & 3;
        cp_wait3();                       // stage i complete
        const float* Ap = ESw + slot * 512;
        ulonglong2 x0 = *(const ulonglong2*)(Ap);
        ulonglong2 x1 = *(const ulonglong2*)(Ap + 128);
        ulonglong2 y0 = *(const ulonglong2*)(Ap + 256);
        ulonglong2 y1 = *(const ulonglong2*)(Ap + 384);
        if (i + 4 < 32) {                 // refill slot for phase i+4
            const float* src = Eg + (i + 4) * 512;
            float* d = ESw + slot * 512;
            cp16(d,       src);
            cp16(d + 128, src + 128);
            cp16(d + 256, src + 256);
            cp16(d + 384, src + 384);
        }
        cp_commit();                      // keep group count aligned
        score2(x0, x1, y0, y1, w0p, w1p, S, (w << 6) + 2 * i, hlane, l);
    }
    __syncthreads();

    // softmax: warp w -> head w; lane owns m = {64j + 2l, +1}, j = 0..7
    const float* Sr  = S + w * 520;
    const float* ser = se + (long)(b * 8 + w) * 262144 + (long)n * 512;
    float v[16];
    float mx = -3.0e38f;
#pragma unroll
    for (int j = 0; j < 8; j++) {
        float2 sv = *(const float2*)(Sr  + j * 64 + l * 2);
        float2 ev = *(const float2*)(ser + j * 64 + l * 2);
        v[2 * j]     = sv.x + ev.x;
        v[2 * j + 1] = sv.y + ev.y;
        mx = fmaxf(mx, fmaxf(v[2 * j], v[2 * j + 1]));
    }
#pragma unroll
    for (int off = 16; off > 0; off >>= 1)
        mx = fmaxf(mx, __shfl_xor_sync(0xFFFFFFFFu, mx, off));

    float sum = 0.f;
#pragma unroll
    for (int j = 0; j < 16; j++) {
        v[j] = __expf(v[j] - mx);
        sum += v[j];
    }
#pragma unroll
    for (int off = 16; off > 0; off >>= 1)
        sum += __shfl_xor_sync(0xFFFFFFFFu, sum, off);

    const float inv = 1.0f / sum;
#pragma unroll
    for (int j = 0; j < 16; j++) v[j] *= inv;

    // PV: hid[w*32 + d] = sum_m v[m] * V[b*512+m][w*32+d]  (packed f32x2)
    const int rg = l >> 3;
    const float* Vb = vmat + (long)b * 131072 + w * 32 + (l & 7) * 4;
    unsigned long long accA, accB;
    {
        float z = 0.f;
        PACK2(accA, z, z);
        PACK2(accB, z, z);
    }
#pragma unroll
    for (int j = 0; j < 8; j++) {
        float s0v = v[2 * j], s1v = v[2 * j + 1];
#pragma unroll
        for (int g = 0; g < 16; g++) {
            int r = j * 64 + g * 4 + rg;
            ulonglong2 V2 = *(const ulonglong2*)(Vb + (long)r * 256);
            int src = g * 2 + (rg >> 1);
            float e0 = __shfl_sync(0xFFFFFFFFu, s0v, src);
            float e1 = __shfl_sync(0xFFFFFFFFu, s1v, src);
            float av = (rg & 1) ? e1 : e0;
            unsigned long long avp;
            PACK2(avp, av, av);
            FMA2(accA, V2.x, avp, accA);
            FMA2(accB, V2.y, avp, accB);
        }
    }
    float4 acc;
    UNPACK2(acc.x, acc.y, accA);
    UNPACK2(acc.z, acc.w, accB);
#pragma unroll
    for (int off = 8; off <= 16; off <<= 1) {
        acc.x += __shfl_xor_sync(0xFFFFFFFFu, acc.x, off);
        acc.y += __shfl_xor_sync(0xFFFFFFFFu, acc.y, off);
        acc.z += __shfl_xor_sync(0xFFFFFFFFu, acc.z, off);
        acc.w += __shfl_xor_sync(0xFFFFFFFFu, acc.w, off);
    }
    if (l < 8)
        *(float4*)(hid + bn * 256 + w * 32 + l * 4) = acc;
}

extern "C" void kernel_launch(void* const* d_in, const int* in_sizes, int n_in,
                              void* d_out, int out_size)
{
    const float* iq    = (const float*)d_in[0];
    const float* ik    = (const float*)d_in[1];
    const float* iv    = (const float*)d_in[2];
    const float* embed = (const float*)d_in[3];
    const float* Wq    = (const float*)d_in[4];
    const float* Wk    = (const float*)d_in[5];
    const float* Wv    = (const float*)d_in[6];
    const float* Wp    = (const float*)d_in[7];
    const float* Wout  = (const float*)d_in[8];
    const float* bout  = (const float*)d_in[9];
    float* out = (float*)d_out;

    float *q, *k, *v, *wq, *se, *hid;
    cudaGetSymbolAddress((void**)&q,   g_q);
    cudaGetSymbolAddress((void**)&k,   g_k);
    cudaGetSymbolAddress((void**)&v,   g_v);
    cudaGetSymbolAddress((void**)&wq,  g_wq);
    cudaGetSymbolAddress((void**)&se,  g_se);
    cudaGetSymbolAddress((void**)&hid, g_hid);

    cudaFuncSetAttribute(k_fused,
                         cudaFuncAttributeMaxDynamicSharedMemorySize,
                         FK_SMEM_BYTES);

    // 1. q/k/v projections (q scaled)
    k_gemm_qkv<<<dim3(32, 4, 3), 512>>>(iq, ik, iv, Wq, Wk, Wv, q, k, v);

    // 2. wq + scores_e (merged, single K-tile)
    k_wq_se<<<dim3(32, 8, 24), 512>>>(q, k, Wp, wq, se);

    // 3. fused scores_p + scores_e + softmax + attn@V -> hidden
    k_fused<<<dim3(512, 2), 256, FK_SMEM_BYTES>>>(embed, wq, se, v, hid);

    // 4. out = hidden @ Wout + bout
    k_gemm_out<<<dim3(32, 4), 512>>>(hid, Wout, out, bout);
}